// round 1
// baseline (speedup 1.0000x reference)
#include <cuda_runtime.h>
#include <cuda_bf16.h>

// ---------------- problem constants ----------------
#define B     512
#define C_IN  12
#define T_IN  5000
#define T1    496      // (5000-50)/10+1
#define T2    95       // (496-25)/5+1
#define NF    32
#define LAT   32
#define HID   64
#define EPSV  1e-5f

// ---------------- scratch (static device memory; no allocation) ----------------
__device__ float g_y1[B * 32 * T1];        // conv1 raw output [b][oc][t]   (~32.5 MB)
__device__ float g_y2t[B * T2 * NF];       // conv2 raw output TRANSPOSED [b][t][f] (~6.2 MB)
__device__ float g_xt[B * T2 * LAT];       // post proj+LN [b][t][l]
__device__ float g_stats1[64];             // sum[32], sumsq[32]
__device__ float g_stats2[64];
__device__ float g_s1[32], g_sh1[32];      // BN1 scale/shift
__device__ float g_s2[32], g_sh2[32];      // BN2 scale/shift

// ---------------- init: zero stats ----------------
__global__ void init_kernel() {
    int i = threadIdx.x;
    if (i < 64) { g_stats1[i] = 0.f; g_stats2[i] = 0.f; }
}

// ---------------- conv1 + BN1 stats ----------------
// grid (8, 512): x = t-tile (64 t's), y = batch. 128 threads.
// thread tile: 4 oc x 4 t.  og = tid>>4 -> oc0 = og*4 ; tg = tid&15 -> t = t0+tg+16*i
__global__ void conv1_kernel(const float* __restrict__ x,
                             const float* __restrict__ w1,
                             const float* __restrict__ b1) {
    __shared__ __align__(16) float xs[680];     // 63*10+50 samples
    __shared__ __align__(16) float ws[1600];    // 32 oc x 50 k
    __shared__ float s_sum[32], s_sq[32];

    const int b    = blockIdx.y;
    const int t0   = blockIdx.x * 64;
    const int tid  = threadIdx.x;
    const int og   = tid >> 4;
    const int tg   = tid & 15;
    const int oc0  = og * 4;

    if (tid < 32) { s_sum[tid] = 0.f; s_sq[tid] = 0.f; }

    float acc[4][4];
#pragma unroll
    for (int j = 0; j < 4; j++)
#pragma unroll
        for (int i = 0; i < 4; i++) acc[j][i] = 0.f;

    for (int c = 0; c < C_IN; c++) {
        __syncthreads();
        // load input segment (zero-padded past T_IN)
        const float* xrow = x + (b * C_IN + c) * T_IN + t0 * 10;
        const int lim = T_IN - t0 * 10;
        for (int s = tid; s < 680; s += 128)
            xs[s] = (s < lim) ? xrow[s] : 0.f;
        // load weights for this input channel: ws[o*50+k]
        for (int idx = tid; idx < 1600; idx += 128) {
            int o = idx / 50, k = idx - o * 50;
            ws[idx] = w1[o * (C_IN * 50) + c * 50 + k];
        }
        __syncthreads();

#pragma unroll
        for (int k = 0; k < 50; k += 2) {
            float2 wv[4], xv[4];
#pragma unroll
            for (int j = 0; j < 4; j++)
                wv[j] = *(const float2*)&ws[(oc0 + j) * 50 + k];
#pragma unroll
            for (int i = 0; i < 4; i++)
                xv[i] = *(const float2*)&xs[(tg + 16 * i) * 10 + k];
#pragma unroll
            for (int j = 0; j < 4; j++)
#pragma unroll
                for (int i = 0; i < 4; i++) {
                    acc[j][i] = fmaf(wv[j].x, xv[i].x, acc[j][i]);
                    acc[j][i] = fmaf(wv[j].y, xv[i].y, acc[j][i]);
                }
        }
    }
    __syncthreads();

    float bias[4];
#pragma unroll
    for (int j = 0; j < 4; j++) bias[j] = b1[oc0 + j];

    float psum[4] = {0.f, 0.f, 0.f, 0.f};
    float psq[4]  = {0.f, 0.f, 0.f, 0.f};
#pragma unroll
    for (int i = 0; i < 4; i++) {
        int t = t0 + tg + 16 * i;
        if (t < T1) {
#pragma unroll
            for (int j = 0; j < 4; j++) {
                float v = acc[j][i] + bias[j];
                g_y1[(b * 32 + oc0 + j) * T1 + t] = v;
                psum[j] += v;
                psq[j]  += v * v;
            }
        }
    }
#pragma unroll
    for (int j = 0; j < 4; j++) {
        atomicAdd(&s_sum[oc0 + j], psum[j]);
        atomicAdd(&s_sq[oc0 + j],  psq[j]);
    }
    __syncthreads();
    if (tid < 32) {
        atomicAdd(&g_stats1[tid],      s_sum[tid]);
        atomicAdd(&g_stats1[32 + tid], s_sq[tid]);
    }
}

// ---------------- BN finalize (which: 0 -> BN1, 1 -> BN2) ----------------
__global__ void finalize_kernel(int which,
                                const float* __restrict__ g,
                                const float* __restrict__ bb) {
    int c = threadIdx.x;
    if (c >= 32) return;
    const float* st = which ? g_stats2 : g_stats1;
    float nInv = which ? (1.f / (float)(B * T2)) : (1.f / (float)(B * T1));
    float mean = st[c] * nInv;
    float var  = st[32 + c] * nInv - mean * mean;
    float s    = g[c] * rsqrtf(var + EPSV);
    if (which) { g_s2[c] = s; g_sh2[c] = bb[c] - mean * s; }
    else       { g_s1[c] = s; g_sh1[c] = bb[c] - mean * s; }
}

// ---------------- conv2 (applies BN1+relu on the fly) + BN2 stats ----------------
// grid 512 (batch). 128 threads. thread tile: 4 oc x 6 t (t = tg + 16*i, i<6, guard t<95)
__global__ void conv2_kernel(const float* __restrict__ w2,
                             const float* __restrict__ b2) {
    __shared__ __align__(16) float zs[500];   // relu(bn1(y1)) row, zero tail
    __shared__ __align__(16) float ws[800];   // 32 oc x 25 k
    __shared__ float s_sum[32], s_sq[32];

    const int b   = blockIdx.x;
    const int tid = threadIdx.x;
    const int og  = tid >> 4;
    const int tg  = tid & 15;
    const int oc0 = og * 4;

    if (tid < 32) { s_sum[tid] = 0.f; s_sq[tid] = 0.f; }

    float acc[4][6];
#pragma unroll
    for (int j = 0; j < 4; j++)
#pragma unroll
        for (int i = 0; i < 6; i++) acc[j][i] = 0.f;

    for (int c = 0; c < 32; c++) {
        __syncthreads();
        float sc = g_s1[c], sh = g_sh1[c];
        const float* yrow = g_y1 + (b * 32 + c) * T1;
        for (int s = tid; s < 500; s += 128) {
            float v = (s < T1) ? fmaf(yrow[s], sc, sh) : 0.f;
            zs[s] = v > 0.f ? v : 0.f;
        }
        for (int idx = tid; idx < 800; idx += 128) {
            int o = idx / 25, k = idx - o * 25;
            ws[idx] = w2[o * (32 * 25) + c * 25 + k];
        }
        __syncthreads();

#pragma unroll
        for (int k = 0; k < 25; k++) {
            float wv[4], xv[6];
#pragma unroll
            for (int j = 0; j < 4; j++) wv[j] = ws[(oc0 + j) * 25 + k];
#pragma unroll
            for (int i = 0; i < 6; i++) xv[i] = zs[(tg + 16 * i) * 5 + k];
#pragma unroll
            for (int j = 0; j < 4; j++)
#pragma unroll
                for (int i = 0; i < 6; i++)
                    acc[j][i] = fmaf(wv[j], xv[i], acc[j][i]);
        }
    }
    __syncthreads();

    float bias[4];
#pragma unroll
    for (int j = 0; j < 4; j++) bias[j] = b2[oc0 + j];

    float psum[4] = {0.f, 0.f, 0.f, 0.f};
    float psq[4]  = {0.f, 0.f, 0.f, 0.f};
#pragma unroll
    for (int i = 0; i < 6; i++) {
        int t = tg + 16 * i;
        if (t < T2) {
#pragma unroll
            for (int j = 0; j < 4; j++) {
                float v = acc[j][i] + bias[j];
                g_y2t[(b * T2 + t) * NF + oc0 + j] = v;   // transposed store
                psum[j] += v;
                psq[j]  += v * v;
            }
        }
    }
#pragma unroll
    for (int j = 0; j < 4; j++) {
        atomicAdd(&s_sum[oc0 + j], psum[j]);
        atomicAdd(&s_sq[oc0 + j],  psq[j]);
    }
    __syncthreads();
    if (tid < 32) {
        atomicAdd(&g_stats2[tid],      s_sum[tid]);
        atomicAdd(&g_stats2[32 + tid], s_sq[tid]);
    }
}

// ---------------- projection + layernorm ----------------
// warp per (b,t) token
__global__ void projln_kernel(const float* __restrict__ pw,
                              const float* __restrict__ pb,
                              const float* __restrict__ lng,
                              const float* __restrict__ lnb) {
    __shared__ float pws[32 * 33];   // pws[f*33 + l] = pw[l*32 + f]
    const int tid = threadIdx.x;
    for (int idx = tid; idx < 1024; idx += blockDim.x)
        pws[(idx & 31) * 33 + (idx >> 5)] = pw[idx];
    __syncthreads();

    const int lane   = tid & 31;
    const int warpId = (blockIdx.x * blockDim.x + tid) >> 5;
    const int nw     = (gridDim.x * blockDim.x) >> 5;

    const float s2  = g_s2[lane], sh2 = g_sh2[lane];
    const float pbv = pb[lane];
    const float lg  = lng[lane], lb = lnb[lane];

    for (int task = warpId; task < B * T2; task += nw) {
        float v = g_y2t[task * NF + lane];
        v = fmaf(v, s2, sh2);
        v = v > 0.f ? v : 0.f;

        float a = pbv;
#pragma unroll
        for (int f = 0; f < 32; f++)
            a = fmaf(__shfl_sync(0xffffffffu, v, f), pws[f * 33 + lane], a);

        // layernorm across the 32 lanes
        float s = a;
#pragma unroll
        for (int off = 16; off > 0; off >>= 1) s += __shfl_xor_sync(0xffffffffu, s, off);
        float mean = s * (1.f / 32.f);
        float d = a - mean;
        float q = d * d;
#pragma unroll
        for (int off = 16; off > 0; off >>= 1) q += __shfl_xor_sync(0xffffffffu, q, off);
        float var = q * (1.f / 32.f);
        g_xt[task * LAT + lane] = fmaf(d * rsqrtf(var + EPSV), lg, lb);
    }
}

// ---------------- PLRNN scan + pool + output projection ----------------
// warp per batch row. grid 64 x 256 threads = 512 warps.
__global__ void recur_kernel(const float* __restrict__ Ain,
                             const float* __restrict__ Win,
                             const float* __restrict__ hbin,
                             const float* __restrict__ owin,
                             const float* __restrict__ obin,
                             float* __restrict__ out) {
    __shared__ float As[32 * 33];    // A[l][m] at As[l*33+m]
    __shared__ float Ws[32 * 65];    // W[m][j] at Ws[m*65+j]
    __shared__ float ows[32 * 33];   // out_w[l][m] at ows[l*33+m]
    __shared__ float hbs[64];

    const int tid = threadIdx.x;
    for (int idx = tid; idx < 1024; idx += 256) {
        As[(idx >> 5) * 33 + (idx & 31)]  = Ain[idx];
        ows[(idx >> 5) * 33 + (idx & 31)] = owin[idx];
    }
    for (int idx = tid; idx < 2048; idx += 256)
        Ws[(idx >> 6) * 65 + (idx & 63)] = Win[idx];
    if (tid < 64) hbs[tid] = hbin[tid];
    __syncthreads();

    const int lane = tid & 31;
    const int b    = blockIdx.x * 8 + (tid >> 5);

    float h = 0.f, sum = 0.f;
    const float* xrow = g_xt + b * T2 * LAT + lane;

    for (int t = 0; t < T2; t++) {
        float xv = xrow[t * LAT];
        float lin = 0.f;
        float p0 = hbs[lane];
        float p1 = hbs[32 + lane];
#pragma unroll
        for (int m = 0; m < 32; m++) {
            float hm = __shfl_sync(0xffffffffu, h, m);
            lin = fmaf(As[lane * 33 + m],      hm, lin);
            p0  = fmaf(Ws[m * 65 + lane],      hm, p0);
            p1  = fmaf(Ws[m * 65 + 32 + lane], hm, p1);
        }
        float r0 = fmaxf(p0, 0.f);
        float r1 = fmaxf(p1, 0.f);
        float nl = 0.f;
#pragma unroll
        for (int j = 0; j < 32; j++)
            nl = fmaf(__shfl_sync(0xffffffffu, r0, j), Ws[lane * 65 + j], nl);
#pragma unroll
        for (int j = 0; j < 32; j++)
            nl = fmaf(__shfl_sync(0xffffffffu, r1, j), Ws[lane * 65 + 32 + j], nl);

        h = lin + nl + xv;
        sum += h;
    }

    float pooled = sum * (1.f / (float)T2);
    float o = obin[lane];
#pragma unroll
    for (int m = 0; m < 32; m++)
        o = fmaf(ows[lane * 33 + m], __shfl_sync(0xffffffffu, pooled, m), o);
    out[b * 32 + lane] = o;
}

// ---------------- launcher ----------------
extern "C" void kernel_launch(void* const* d_in, const int* in_sizes, int n_in,
                              void* d_out, int out_size) {
    const float* x       = (const float*)d_in[0];
    const float* conv1_w = (const float*)d_in[1];
    const float* conv1_b = (const float*)d_in[2];
    const float* bn1_g   = (const float*)d_in[3];
    const float* bn1_b   = (const float*)d_in[4];
    const float* conv2_w = (const float*)d_in[5];
    const float* conv2_b = (const float*)d_in[6];
    const float* bn2_g   = (const float*)d_in[7];
    const float* bn2_b   = (const float*)d_in[8];
    const float* proj_w  = (const float*)d_in[9];
    const float* proj_b  = (const float*)d_in[10];
    const float* ln_g    = (const float*)d_in[11];
    const float* ln_b    = (const float*)d_in[12];
    const float* A       = (const float*)d_in[13];
    const float* W       = (const float*)d_in[14];
    const float* h_bias  = (const float*)d_in[15];
    const float* out_w   = (const float*)d_in[16];
    const float* out_b   = (const float*)d_in[17];
    float* out = (float*)d_out;

    init_kernel<<<1, 64>>>();
    conv1_kernel<<<dim3(8, B), 128>>>(x, conv1_w, conv1_b);
    finalize_kernel<<<1, 32>>>(0, bn1_g, bn1_b);
    conv2_kernel<<<B, 128>>>(conv2_w, conv2_b);
    finalize_kernel<<<1, 32>>>(1, bn2_g, bn2_b);
    projln_kernel<<<512, 256>>>(proj_w, proj_b, ln_g, ln_b);
    recur_kernel<<<64, 256>>>(A, W, h_bias, out_w, out_b, out);
}